// round 3
// baseline (speedup 1.0000x reference)
#include <cuda_runtime.h>
#include <cuda_bf16.h>
#include <cstdint>

#define BATCH 512
#define FEAT  512
#define GRP   8
#define NBLK  32           // 2 groups (16 rows) per block

// Device scratch
__device__ __nv_bfloat16 g_ftb[BATCH * FEAT];
__device__ float g_partial[NBLK];
__device__ int   g_count = 0;

// Shared layout (dynamic): Bs double-buffered k64 slabs, As, Ssm
#define BS_STR 72                         // 64 data + 8 pad bf16 (conflict-free ldmatrix)
#define AS_STR 520                        // 512 + 8 pad bf16
#define SS_STR 520                        // 512 + 8 pad fp32
#define BS_BYTES (2 * BATCH * BS_STR * 2) // 147456
#define AS_BYTES (16 * AS_STR * 2)        // 16640
#define SS_BYTES (16 * SS_STR * 4)        // 33280
#define SMEM_TOTAL (BS_BYTES + AS_BYTES + SS_BYTES)
#define NSLAB 8                           // 512 / 64

#define CPA16(dst, src) \
    asm volatile("cp.async.cg.shared.global [%0], [%1], 16;\n" :: "r"(dst), "l"(src))

// ---------------------------------------------------------------------------
// Kernel 0: f_t -> bf16
// ---------------------------------------------------------------------------
__global__ void __launch_bounds__(256) convert_ft(const float* __restrict__ ft) {
    const int idx = blockIdx.x * 256 + threadIdx.x;   // 0..65535 float4
    const float4 t = ((const float4*)ft)[idx];
    __nv_bfloat162* to = (__nv_bfloat162*)g_ftb;
    to[2 * idx + 0] = __floats2bfloat162_rn(t.x, t.y);
    to[2 * idx + 1] = __floats2bfloat162_rn(t.z, t.w);
}

// ---------------------------------------------------------------------------
// Kernel 1: fused GEMM-slice + group stats + final reduction.
// Block b computes S rows [16b, 16b+16) = f_s-rows @ f_t^T via mma.m16n8k16,
// streaming f_t (bf16) in k64 slabs with cp.async double buffering.
// ---------------------------------------------------------------------------
__global__ void __launch_bounds__(256, 1) fused_kernel(const float* __restrict__ fs,
                                                       float* __restrict__ out) {
    extern __shared__ __align__(16) char smem[];
    __nv_bfloat16 (*Bs)[BATCH][BS_STR] = (__nv_bfloat16(*)[BATCH][BS_STR])smem;
    __nv_bfloat16 (*As)[AS_STR]        = (__nv_bfloat16(*)[AS_STR])(smem + BS_BYTES);
    float (*Ssm)[SS_STR]               = (float(*)[SS_STR])(smem + BS_BYTES + AS_BYTES);
    __shared__ float rk_sm[128];
    __shared__ float wsum[4];

    const int tid  = threadIdx.x;
    const int warp = tid >> 5;
    const int lane = tid & 31;
    const int m0   = blockIdx.x * 16;

    // ---- Load + convert this block's 16 f_s rows into As (bf16) ----
    #pragma unroll
    for (int t = 0; t < 8; t++) {
        const int idx = tid + t * 256;          // 0..2047 float4
        const int row = idx >> 7;               // 0..15
        const int c4  = idx & 127;              // 0..127
        const float4 v = *(const float4*)(fs + (m0 + row) * FEAT + c4 * 4);
        __nv_bfloat162* dst = (__nv_bfloat162*)&As[row][c4 * 4];
        dst[0] = __floats2bfloat162_rn(v.x, v.y);
        dst[1] = __floats2bfloat162_rn(v.z, v.w);
    }

    // ---- cp.async slab loader: slab s = f_t[:, 64s..64s+63] bf16 ----
    auto issue_slab = [&](int s, int buf) {
        #pragma unroll
        for (int v = 0; v < 16; v++) {
            const int c    = tid + v * 256;     // 0..4095 16B-chunks
            const int n    = c >> 3;
            const int part = c & 7;
            const __nv_bfloat16* src = g_ftb + n * FEAT + s * 64 + part * 8;
            const uint32_t dst =
                (uint32_t)__cvta_generic_to_shared(&Bs[buf][n][part * 8]);
            CPA16(dst, src);
        }
        asm volatile("cp.async.commit_group;\n");
    };

    issue_slab(0, 0);
    issue_slab(1, 1);

    // ldmatrix lane addressing (validated in round 2)
    const int a_row = (lane & 7) + ((lane >> 3) & 1) * 8;
    const int a_k8  = (lane >> 4) * 8;
    const int b_ro  = (lane & 7) + (lane >> 4) * 8;
    const int b_k8  = ((lane >> 3) & 1) * 8;

    float acc[8][4] = {};   // 8 n8-tiles: cols warp*64 + nt*8

    #pragma unroll 1
    for (int s = 0; s < NSLAB; s++) {
        const int buf = s & 1;
        if (s + 1 < NSLAB) { asm volatile("cp.async.wait_group 1;\n"); }
        else               { asm volatile("cp.async.wait_group 0;\n"); }
        __syncthreads();

        #pragma unroll
        for (int kk = 0; kk < 4; kk++) {
            const int k = kk * 16;
            uint32_t a0, a1, a2, a3;
            {
                uint32_t aaddr = (uint32_t)__cvta_generic_to_shared(
                    &As[a_row][s * 64 + k + a_k8]);
                asm volatile("ldmatrix.sync.aligned.m8n8.x4.shared.b16 {%0,%1,%2,%3}, [%4];\n"
                             : "=r"(a0), "=r"(a1), "=r"(a2), "=r"(a3) : "r"(aaddr));
            }
            #pragma unroll
            for (int ntp = 0; ntp < 4; ntp++) {
                uint32_t b0, b1, b2, b3;
                uint32_t baddr = (uint32_t)__cvta_generic_to_shared(
                    &Bs[buf][warp * 64 + ntp * 16 + b_ro][k + b_k8]);
                asm volatile("ldmatrix.sync.aligned.m8n8.x4.shared.b16 {%0,%1,%2,%3}, [%4];\n"
                             : "=r"(b0), "=r"(b1), "=r"(b2), "=r"(b3) : "r"(baddr));
                float* c0 = acc[2 * ntp];
                float* c1 = acc[2 * ntp + 1];
                asm volatile("mma.sync.aligned.m16n8k16.row.col.f32.bf16.bf16.f32 "
                             "{%0,%1,%2,%3}, {%4,%5,%6,%7}, {%8,%9}, {%0,%1,%2,%3};\n"
                             : "+f"(c0[0]), "+f"(c0[1]), "+f"(c0[2]), "+f"(c0[3])
                             : "r"(a0), "r"(a1), "r"(a2), "r"(a3), "r"(b0), "r"(b1));
                asm volatile("mma.sync.aligned.m16n8k16.row.col.f32.bf16.bf16.f32 "
                             "{%0,%1,%2,%3}, {%4,%5,%6,%7}, {%8,%9}, {%0,%1,%2,%3};\n"
                             : "+f"(c1[0]), "+f"(c1[1]), "+f"(c1[2]), "+f"(c1[3])
                             : "r"(a0), "r"(a1), "r"(a2), "r"(a3), "r"(b2), "r"(b3));
            }
        }
        __syncthreads();   // all warps done with buf before refill
        if (s + 2 < NSLAB) issue_slab(s + 2, buf);
    }

    // ---- Write warp tiles to Ssm ----
    {
        const int g  = lane >> 2;
        const int t2 = (lane & 3) * 2;
        #pragma unroll
        for (int nt = 0; nt < 8; nt++) {
            const int c = warp * 64 + nt * 8 + t2;
            *(float2*)&Ssm[g][c]     = make_float2(acc[nt][0], acc[nt][1]);
            *(float2*)&Ssm[g + 8][c] = make_float2(acc[nt][2], acc[nt][3]);
        }
    }
    __syncthreads();

    // ---- rk: 16 rows x 8 group-cols; 16 threads per row, each covers 32 j ----
    {
        const int r   = tid >> 4;                      // 0..15
        const int sub = tid & 15;                      // 0..15
        const int gl  = r >> 3;                        // local group
        const int cb  = (blockIdx.x * 2 + gl) * GRP;   // group col base
        float sref[8];
        #pragma unroll
        for (int i = 0; i < 8; i++) sref[i] = Ssm[r][cb + i];
        float sums[8] = {};
        const float4* rowp = (const float4*)&Ssm[r][0];
        #pragma unroll
        for (int f = 0; f < 8; f++) {
            const float4 v = rowp[sub * 8 + f];
            #pragma unroll
            for (int i = 0; i < 8; i++) {
                sums[i] += fmaxf(v.x - sref[i], 0.f) + fmaxf(v.y - sref[i], 0.f)
                         + fmaxf(v.z - sref[i], 0.f) + fmaxf(v.w - sref[i], 0.f);
            }
        }
        #pragma unroll
        for (int o = 8; o > 0; o >>= 1)
            #pragma unroll
            for (int i = 0; i < 8; i++)
                sums[i] += __shfl_down_sync(0xffffffffu, sums[i], o, 16);
        if (sub == 0) {
            #pragma unroll
            for (int i = 0; i < 8; i++) rk_sm[r * 8 + i] = 1.f + sums[i];
        }
    }
    __syncthreads();

    // ---- pos ranks + ratios (128 threads: (gl, i, j)) ----
    float ratio = 0.f;
    if (tid < 128) {
        const int gl = tid >> 6;
        const int i  = (tid >> 3) & 7;
        const int j  = tid & 7;
        const int r  = gl * 8 + i;
        const int cb = (blockIdx.x * 2 + gl) * GRP;
        const float* prow = &Ssm[r][cb];
        const float pij = prow[j];
        float ps = 0.f;
        #pragma unroll
        for (int k = 0; k < GRP; k++) ps += fmaxf(prow[k] - pij, 0.f);
        ratio = (1.f + ps) / rk_sm[r * 8 + j];
    }
    #pragma unroll
    for (int o = 16; o > 0; o >>= 1)
        ratio += __shfl_down_sync(0xffffffffu, ratio, o);
    if (tid < 128 && lane == 0) wsum[warp] = ratio;
    __syncthreads();

    // ---- block partial + last-block final reduction (deterministic order) ----
    if (tid == 0) {
        g_partial[blockIdx.x] = wsum[0] + wsum[1] + wsum[2] + wsum[3];
        __threadfence();
        const int prev = atomicAdd(&g_count, 1);
        if (prev == NBLK - 1) {
            __threadfence();
            float tot = 0.f;
            #pragma unroll
            for (int b = 0; b < NBLK; b++)
                tot += *((volatile float*)&g_partial[b]);
            out[0] = 1.f - tot * (1.f / 4096.f);
            g_count = 0;   // reset for next replay
        }
    }
}

extern "C" void kernel_launch(void* const* d_in, const int* in_sizes, int n_in,
                              void* d_out, int out_size) {
    const float* fs = (const float*)d_in[0];
    const float* ft = (const float*)d_in[1];
    float* out = (float*)d_out;

    cudaFuncSetAttribute(fused_kernel,
                         cudaFuncAttributeMaxDynamicSharedMemorySize, SMEM_TOTAL);
    convert_ft<<<256, 256>>>(ft);
    fused_kernel<<<NBLK, 256, SMEM_TOTAL>>>(fs, out);
}

// round 4
// speedup vs baseline: 1.2542x; 1.2542x over previous
#include <cuda_runtime.h>
#include <cuda_bf16.h>
#include <cstdint>

#define BATCH 512
#define FEAT  512
#define NID   64
#define GRP   8

__device__ float g_S[BATCH * BATCH];
__device__ float g_partial[NID];
__device__ int   g_count = 0;

// ---------------------------------------------------------------------------
// Kernel 1: S = f_s @ f_t^T, fp32 inputs converted to bf16 inline, HMMA core.
// BM=64, BN=32, BK=64. 256 threads = 8 warps (4m x 2n), warp tile 16x16.
// Grid (16, 8) = 128 blocks. Double-buffered smem, register prefetch,
// ONE __syncthreads per k-slab.
// ---------------------------------------------------------------------------
__global__ void __launch_bounds__(256) gemm_kernel(const float* __restrict__ fs,
                                                   const float* __restrict__ ft) {
    __shared__ __align__(16) __nv_bfloat16 As[2][64][72];  // +8 bf16 pad: conflict-free
    __shared__ __align__(16) __nv_bfloat16 Bs[2][32][72];

    const int tid   = threadIdx.x;
    const int mTile = blockIdx.y * 64;
    const int nTile = blockIdx.x * 32;
    const int warp  = tid >> 5;
    const int lane  = tid & 31;
    const int wm    = warp & 3;
    const int wn    = warp >> 2;

    // A loader: row = tid>>2 (0..63), kc = (tid&3)*16 -> 16 floats (4 float4)
    const int arow = tid >> 2, akc = (tid & 3) * 16;
    // B loader: row = tid>>3 (0..31), kc = (tid&7)*8 -> 8 floats (2 float4)
    const int brow = tid >> 3, bkc = (tid & 7) * 8;

    const float* agp = fs + (mTile + arow) * FEAT + akc;
    const float* bgp = ft + (nTile + brow) * FEAT + bkc;

    float4 pa[4], pb[2];
    #pragma unroll
    for (int i = 0; i < 4; i++) pa[i] = *(const float4*)(agp + i * 4);
    #pragma unroll
    for (int i = 0; i < 2; i++) pb[i] = *(const float4*)(bgp + i * 4);

    float acc[2][4] = {};

    const int a_row = 16 * wm + (lane & 7) + ((lane >> 3) & 1) * 8;
    const int a_k8  = (lane >> 4) * 8;
    const int b_row = 16 * wn + (lane & 7) + (lane >> 4) * 8;
    const int b_k8  = ((lane >> 3) & 1) * 8;

    #pragma unroll 1
    for (int s = 0; s < 8; s++) {
        const int buf = s & 1;
        // commit prefetched fp32 regs to smem as bf16
        {
            __nv_bfloat162 c[8];
            #pragma unroll
            for (int i = 0; i < 4; i++) {
                c[2*i+0] = __floats2bfloat162_rn(pa[i].x, pa[i].y);
                c[2*i+1] = __floats2bfloat162_rn(pa[i].z, pa[i].w);
            }
            *(uint4*)&As[buf][arow][akc]     = *(uint4*)&c[0];
            *(uint4*)&As[buf][arow][akc + 8] = *(uint4*)&c[4];
            __nv_bfloat162 d[4];
            #pragma unroll
            for (int i = 0; i < 2; i++) {
                d[2*i+0] = __floats2bfloat162_rn(pb[i].x, pb[i].y);
                d[2*i+1] = __floats2bfloat162_rn(pb[i].z, pb[i].w);
            }
            *(uint4*)&Bs[buf][brow][bkc] = *(uint4*)&d[0];
        }
        __syncthreads();

        if (s < 7) {
            #pragma unroll
            for (int i = 0; i < 4; i++) pa[i] = *(const float4*)(agp + (s + 1) * 64 + i * 4);
            #pragma unroll
            for (int i = 0; i < 2; i++) pb[i] = *(const float4*)(bgp + (s + 1) * 64 + i * 4);
        }

        #pragma unroll
        for (int kk = 0; kk < 4; kk++) {
            const int k = kk * 16;
            uint32_t a0, a1, a2, a3, b0, b1, b2, b3;
            uint32_t aaddr = (uint32_t)__cvta_generic_to_shared(&As[buf][a_row][k + a_k8]);
            uint32_t baddr = (uint32_t)__cvta_generic_to_shared(&Bs[buf][b_row][k + b_k8]);
            asm volatile("ldmatrix.sync.aligned.m8n8.x4.shared.b16 {%0,%1,%2,%3}, [%4];\n"
                         : "=r"(a0), "=r"(a1), "=r"(a2), "=r"(a3) : "r"(aaddr));
            asm volatile("ldmatrix.sync.aligned.m8n8.x4.shared.b16 {%0,%1,%2,%3}, [%4];\n"
                         : "=r"(b0), "=r"(b1), "=r"(b2), "=r"(b3) : "r"(baddr));
            asm volatile("mma.sync.aligned.m16n8k16.row.col.f32.bf16.bf16.f32 "
                         "{%0,%1,%2,%3}, {%4,%5,%6,%7}, {%8,%9}, {%0,%1,%2,%3};\n"
                         : "+f"(acc[0][0]), "+f"(acc[0][1]), "+f"(acc[0][2]), "+f"(acc[0][3])
                         : "r"(a0), "r"(a1), "r"(a2), "r"(a3), "r"(b0), "r"(b1));
            asm volatile("mma.sync.aligned.m16n8k16.row.col.f32.bf16.bf16.f32 "
                         "{%0,%1,%2,%3}, {%4,%5,%6,%7}, {%8,%9}, {%0,%1,%2,%3};\n"
                         : "+f"(acc[1][0]), "+f"(acc[1][1]), "+f"(acc[1][2]), "+f"(acc[1][3])
                         : "r"(a0), "r"(a1), "r"(a2), "r"(a3), "r"(b2), "r"(b3));
        }
    }

    const int g = lane >> 2, t = lane & 3;
    const int row0 = mTile + 16 * wm + g;
    #pragma unroll
    for (int h = 0; h < 2; h++) {
        const int col = nTile + 16 * wn + 8 * h + t * 2;
        *(float2*)&g_S[row0 * BATCH + col]       = make_float2(acc[h][0], acc[h][1]);
        *(float2*)&g_S[(row0 + 8) * BATCH + col] = make_float2(acc[h][2], acc[h][3]);
    }
}

// ---------------------------------------------------------------------------
// Kernel 2: per-group stats + fused final reduction (last block).
// ---------------------------------------------------------------------------
__global__ void __launch_bounds__(256) group_final_kernel(float* __restrict__ out) {
    __shared__ float Sr[GRP * BATCH];
    __shared__ float rk_sm[64];
    __shared__ float wsum[2];

    const int n   = blockIdx.x;
    const int tid = threadIdx.x;

    {
        const float4* src = (const float4*)(g_S + n * GRP * BATCH);
        float4* dst = (float4*)Sr;
        #pragma unroll
        for (int v = 0; v < 4; v++) dst[tid + v * 256] = src[tid + v * 256];
    }
    __syncthreads();

    const int p = tid >> 2;
    const int q = tid & 3;
    const int r = p >> 3;
    const int i = p & 7;
    const float sbi = Sr[r * BATCH + n * GRP + i];
    const float* row = Sr + r * BATCH;

    float s = 0.f;
    #pragma unroll 8
    for (int jj = 0; jj < BATCH; jj += 16) {
        float4 v = *(const float4*)(row + jj + q * 4);
        s += fmaxf(v.x - sbi, 0.f) + fmaxf(v.y - sbi, 0.f)
           + fmaxf(v.z - sbi, 0.f) + fmaxf(v.w - sbi, 0.f);
    }
    s += __shfl_down_sync(0xffffffffu, s, 1);
    s += __shfl_down_sync(0xffffffffu, s, 2);
    if (q == 0) rk_sm[p] = 1.f + s;
    __syncthreads();

    float ratio = 0.f;
    if (tid < 64) {
        const int i2 = tid >> 3;
        const int j2 = tid & 7;
        const float* prow = Sr + i2 * BATCH + n * GRP;
        const float pij = prow[j2];
        float ps = 0.f;
        #pragma unroll
        for (int k = 0; k < GRP; k++) ps += fmaxf(prow[k] - pij, 0.f);
        ratio = (1.f + ps) / rk_sm[tid];
    }
    #pragma unroll
    for (int o = 16; o > 0; o >>= 1)
        ratio += __shfl_down_sync(0xffffffffu, ratio, o);
    if (tid < 64 && (tid & 31) == 0) wsum[tid >> 5] = ratio;
    __syncthreads();

    // last-block-done final reduction (deterministic fixed-order sum)
    if (tid == 0) {
        g_partial[n] = wsum[0] + wsum[1];
        __threadfence();
        const int prev = atomicAdd(&g_count, 1);
        if (prev == NID - 1) {
            __threadfence();
            float tot = 0.f;
            #pragma unroll
            for (int b = 0; b < NID; b++)
                tot += *((volatile float*)&g_partial[b]);
            out[0] = 1.f - tot * (1.f / 4096.f);
            g_count = 0;   // reset for next replay
        }
    }
}

extern "C" void kernel_launch(void* const* d_in, const int* in_sizes, int n_in,
                              void* d_out, int out_size) {
    const float* fs = (const float*)d_in[0];
    const float* ft = (const float*)d_in[1];
    float* out = (float*)d_out;

    gemm_kernel<<<dim3(16, 8), 256>>>(fs, ft);
    group_final_kernel<<<NID, 256>>>(out);
}

// round 5
// speedup vs baseline: 1.2569x; 1.0021x over previous
#include <cuda_runtime.h>
#include <cuda_bf16.h>
#include <cstdint>

#define BATCH 512
#define FEAT  512
#define NBLK  128

__device__ float g_S[BATCH * BATCH];
__device__ float g_partial[NBLK];
__device__ unsigned g_ctr  = 0;
__device__ volatile unsigned g_epoch = 0;
__device__ unsigned g_done = 0;

// ---------------------------------------------------------------------------
// Single fused kernel:
//   Phase 1: S = f_s @ f_t^T (bf16 HMMA, inline fp32->bf16 convert) — 128 blocks
//   Grid barrier (epoch-based; all 128 CTAs co-resident at 1 CTA/SM)
//   Phase 2: 4 rows per block, register-resident row stats + ratios
//   Last-block-done deterministic final reduction.
// ---------------------------------------------------------------------------
__global__ void __launch_bounds__(256, 1) fused_kernel(const float* __restrict__ fs,
                                                       const float* __restrict__ ft,
                                                       float* __restrict__ out) {
    __shared__ __align__(16) __nv_bfloat16 As[2][64][72];
    __shared__ __align__(16) __nv_bfloat16 Bs[2][32][72];
    __shared__ float refs[4][8];
    __shared__ float wr[8][8];
    __shared__ float warp_sums[8];
    __shared__ unsigned ep0_sm;
    __shared__ int last_sm;

    const int tid   = threadIdx.x;
    const int bid   = blockIdx.y * 16 + blockIdx.x;
    const int mTile = blockIdx.y * 64;
    const int nTile = blockIdx.x * 32;
    const int warp  = tid >> 5;
    const int lane  = tid & 31;
    const int wm    = warp & 3;
    const int wn    = warp >> 2;

    if (tid == 0) ep0_sm = g_epoch;   // baseline epoch (safe: bump needs our arrival)

    // ================= Phase 1: GEMM (identical math to round 4) =============
    const int arow = tid >> 2, akc = (tid & 3) * 16;
    const int brow = tid >> 3, bkc = (tid & 7) * 8;
    const float* agp = fs + (mTile + arow) * FEAT + akc;
    const float* bgp = ft + (nTile + brow) * FEAT + bkc;

    float4 pa[4], pb[2];
    #pragma unroll
    for (int i = 0; i < 4; i++) pa[i] = *(const float4*)(agp + i * 4);
    #pragma unroll
    for (int i = 0; i < 2; i++) pb[i] = *(const float4*)(bgp + i * 4);

    float acc[2][4] = {};
    const int a_row = 16 * wm + (lane & 7) + ((lane >> 3) & 1) * 8;
    const int a_k8  = (lane >> 4) * 8;
    const int b_row = 16 * wn + (lane & 7) + (lane >> 4) * 8;
    const int b_k8  = ((lane >> 3) & 1) * 8;

    #pragma unroll 1
    for (int s = 0; s < 8; s++) {
        const int buf = s & 1;
        {
            __nv_bfloat162 c[8];
            #pragma unroll
            for (int i = 0; i < 4; i++) {
                c[2*i+0] = __floats2bfloat162_rn(pa[i].x, pa[i].y);
                c[2*i+1] = __floats2bfloat162_rn(pa[i].z, pa[i].w);
            }
            *(uint4*)&As[buf][arow][akc]     = *(uint4*)&c[0];
            *(uint4*)&As[buf][arow][akc + 8] = *(uint4*)&c[4];
            __nv_bfloat162 d[4];
            #pragma unroll
            for (int i = 0; i < 2; i++) {
                d[2*i+0] = __floats2bfloat162_rn(pb[i].x, pb[i].y);
                d[2*i+1] = __floats2bfloat162_rn(pb[i].z, pb[i].w);
            }
            *(uint4*)&Bs[buf][brow][bkc] = *(uint4*)&d[0];
        }
        __syncthreads();

        if (s < 7) {
            #pragma unroll
            for (int i = 0; i < 4; i++) pa[i] = *(const float4*)(agp + (s + 1) * 64 + i * 4);
            #pragma unroll
            for (int i = 0; i < 2; i++) pb[i] = *(const float4*)(bgp + (s + 1) * 64 + i * 4);
        }

        #pragma unroll
        for (int kk = 0; kk < 4; kk++) {
            const int k = kk * 16;
            uint32_t a0, a1, a2, a3, b0, b1, b2, b3;
            uint32_t aaddr = (uint32_t)__cvta_generic_to_shared(&As[buf][a_row][k + a_k8]);
            uint32_t baddr = (uint32_t)__cvta_generic_to_shared(&Bs[buf][b_row][k + b_k8]);
            asm volatile("ldmatrix.sync.aligned.m8n8.x4.shared.b16 {%0,%1,%2,%3}, [%4];\n"
                         : "=r"(a0), "=r"(a1), "=r"(a2), "=r"(a3) : "r"(aaddr));
            asm volatile("ldmatrix.sync.aligned.m8n8.x4.shared.b16 {%0,%1,%2,%3}, [%4];\n"
                         : "=r"(b0), "=r"(b1), "=r"(b2), "=r"(b3) : "r"(baddr));
            asm volatile("mma.sync.aligned.m16n8k16.row.col.f32.bf16.bf16.f32 "
                         "{%0,%1,%2,%3}, {%4,%5,%6,%7}, {%8,%9}, {%0,%1,%2,%3};\n"
                         : "+f"(acc[0][0]), "+f"(acc[0][1]), "+f"(acc[0][2]), "+f"(acc[0][3])
                         : "r"(a0), "r"(a1), "r"(a2), "r"(a3), "r"(b0), "r"(b1));
            asm volatile("mma.sync.aligned.m16n8k16.row.col.f32.bf16.bf16.f32 "
                         "{%0,%1,%2,%3}, {%4,%5,%6,%7}, {%8,%9}, {%0,%1,%2,%3};\n"
                         : "+f"(acc[1][0]), "+f"(acc[1][1]), "+f"(acc[1][2]), "+f"(acc[1][3])
                         : "r"(a0), "r"(a1), "r"(a2), "r"(a3), "r"(b2), "r"(b3));
        }
        __syncthreads();
    }

    {
        const int g = lane >> 2, t = lane & 3;
        const int row0 = mTile + 16 * wm + g;
        #pragma unroll
        for (int h = 0; h < 2; h++) {
            const int col = nTile + 16 * wn + 8 * h + t * 2;
            *(float2*)&g_S[row0 * BATCH + col]       = make_float2(acc[h][0], acc[h][1]);
            *(float2*)&g_S[(row0 + 8) * BATCH + col] = make_float2(acc[h][2], acc[h][3]);
        }
    }
    __syncthreads();

    // ================= Grid barrier (epoch-based) ============================
    if (tid == 0) {
        __threadfence();
        const unsigned ep0 = ep0_sm;
        const unsigned prev = atomicAdd(&g_ctr, 1);
        if (prev == NBLK - 1) {
            g_ctr = 0;                 // safe: others spin on epoch, not ctr
            __threadfence();
            g_epoch = ep0 + 1;
        } else {
            while (g_epoch == ep0) {}
        }
        __threadfence();
    }
    __syncthreads();

    // ================= Phase 2: 4 rows per block, register-resident ==========
    const int row_l = tid >> 6;                 // 0..3
    const int c     = tid & 63;                 // 0..63 (float4 chunk)
    const int r     = bid * 4 + row_l;          // global row 0..511
    const float4* S4 = (const float4*)(g_S + r * BATCH);
    const float4 v1 = S4[c];
    const float4 v2 = S4[c + 64];

    const int b0  = r & ~7;                     // group column base
    const int rc0 = b0 >> 2;                    // first ref chunk index
    if (rc0 < 64) {
        if (c == rc0)      *(float4*)&refs[row_l][0] = v1;
        if (c == rc0 + 1)  *(float4*)&refs[row_l][4] = v1;
    } else {
        if (c == rc0 - 64) *(float4*)&refs[row_l][0] = v2;
        if (c == rc0 - 63) *(float4*)&refs[row_l][4] = v2;
    }
    __syncthreads();

    float p[8];
    #pragma unroll
    for (int j = 0; j < 8; j++) p[j] = refs[row_l][j];

    float s8[8];
    #pragma unroll
    for (int j = 0; j < 8; j++) {
        s8[j] = fmaxf(v1.x - p[j], 0.f) + fmaxf(v1.y - p[j], 0.f)
              + fmaxf(v1.z - p[j], 0.f) + fmaxf(v1.w - p[j], 0.f)
              + fmaxf(v2.x - p[j], 0.f) + fmaxf(v2.y - p[j], 0.f)
              + fmaxf(v2.z - p[j], 0.f) + fmaxf(v2.w - p[j], 0.f);
    }
    #pragma unroll
    for (int o = 16; o > 0; o >>= 1)
        #pragma unroll
        for (int j = 0; j < 8; j++)
            s8[j] += __shfl_down_sync(0xffffffffu, s8[j], o);
    if (lane == 0) {
        #pragma unroll
        for (int j = 0; j < 8; j++) wr[warp][j] = s8[j];
    }
    __syncthreads();

    float ratio = 0.f;
    if (tid < 32) {
        const int rl = tid >> 3, j = tid & 7;
        const float rk = 1.f + wr[rl * 2][j] + wr[rl * 2 + 1][j];
        const float pj = refs[rl][j];
        float ps = 0.f;
        #pragma unroll
        for (int k = 0; k < 8; k++) ps += fmaxf(refs[rl][k] - pj, 0.f);
        ratio = (1.f + ps) / rk;
    }
    #pragma unroll
    for (int o = 16; o > 0; o >>= 1)
        ratio += __shfl_down_sync(0xffffffffu, ratio, o);

    if (tid == 0) {
        g_partial[bid] = ratio;
        __threadfence();
        const unsigned prev = atomicAdd(&g_done, 1);
        last_sm = (prev == NBLK - 1) ? 1 : 0;
        if (last_sm) __threadfence();
    }
    __syncthreads();

    // ================= Last block: deterministic final reduction =============
    if (last_sm) {
        float v = (tid < NBLK) ? g_partial[tid] : 0.f;
        #pragma unroll
        for (int o = 16; o > 0; o >>= 1)
            v += __shfl_down_sync(0xffffffffu, v, o);
        if (lane == 0) warp_sums[warp] = v;
        __syncthreads();
        if (tid == 0) {
            float tot = 0.f;
            #pragma unroll
            for (int w = 0; w < 8; w++) tot += warp_sums[w];
            out[0] = 1.f - tot * (1.f / 4096.f);
            g_done = 0;   // reset for next replay
        }
    }
}

extern "C" void kernel_launch(void* const* d_in, const int* in_sizes, int n_in,
                              void* d_out, int out_size) {
    const float* fs = (const float*)d_in[0];
    const float* ft = (const float*)d_in[1];
    float* out = (float*)d_out;

    fused_kernel<<<dim3(16, 8), 256>>>(fs, ft, out);
}

// round 6
// speedup vs baseline: 1.4545x; 1.1572x over previous
#include <cuda_runtime.h>
#include <cuda_bf16.h>
#include <cstdint>

#define BATCH 512
#define FEAT  512
#define NBLK  128

#define AS_STR 520                       // 512 + 8 bf16 pad (1040B ≡ 1 mod 8 banks)
#define AS_BYTES (64 * AS_STR * 2)       // 66560
#define BS_BYTES (32 * AS_STR * 2)       // 33280
#define SMEM_TOTAL (AS_BYTES + BS_BYTES) // 99840

__device__ float g_S[BATCH * BATCH];
__device__ float g_partial[NBLK];
__device__ unsigned g_ctr  = 0;
__device__ volatile unsigned g_epoch = 0;
__device__ unsigned g_done = 0;

// ---------------------------------------------------------------------------
// Single fused kernel, full-K smem-resident GEMM (NO mainloop syncs):
//   Stage: whole A (64x512) + B (32x512) tiles -> smem as bf16, high-MLP LDG.
//   Mainloop: 32 k16-steps of ldmatrix+MMA, zero __syncthreads.
//   Grid barrier, then register-resident phase 2 (validated round 5).
// ---------------------------------------------------------------------------
__global__ void __launch_bounds__(256, 1) fused_kernel(const float* __restrict__ fs,
                                                       const float* __restrict__ ft,
                                                       float* __restrict__ out) {
    extern __shared__ __align__(16) char smem[];
    __nv_bfloat16 (*As)[AS_STR] = (__nv_bfloat16(*)[AS_STR])smem;
    __nv_bfloat16 (*Bs)[AS_STR] = (__nv_bfloat16(*)[AS_STR])(smem + AS_BYTES);

    __shared__ float refs[4][8];
    __shared__ float wr[8][8];
    __shared__ float warp_sums[8];
    __shared__ unsigned ep0_sm;
    __shared__ int last_sm;

    const int tid   = threadIdx.x;
    const int bid   = blockIdx.y * 16 + blockIdx.x;
    const int mTile = blockIdx.y * 64;
    const int nTile = blockIdx.x * 32;
    const int warp  = tid >> 5;
    const int lane  = tid & 31;
    const int wm    = warp & 3;
    const int wn    = warp >> 2;

    if (tid == 0) ep0_sm = g_epoch;

    // ================= Stage A and B tiles (fp32 -> bf16) ====================
    // A: 64 rows x 128 float4-chunks = 8192 chunks; B: 32 x 128 = 4096 chunks.
    {
        const float4* ag = (const float4*)(fs + mTile * FEAT);
        #pragma unroll 8
        for (int v = 0; v < 32; v++) {
            const int idx = tid + v * 256;
            const int row = idx >> 7, c4 = idx & 127;
            const float4 x = ag[row * 128 + c4];
            __nv_bfloat162 h0 = __floats2bfloat162_rn(x.x, x.y);
            __nv_bfloat162 h1 = __floats2bfloat162_rn(x.z, x.w);
            uint2 pk = make_uint2(*(uint32_t*)&h0, *(uint32_t*)&h1);
            *(uint2*)&As[row][c4 * 4] = pk;
        }
        const float4* bg = (const float4*)(ft + nTile * FEAT);
        #pragma unroll 8
        for (int v = 0; v < 16; v++) {
            const int idx = tid + v * 256;
            const int row = idx >> 7, c4 = idx & 127;
            const float4 x = bg[row * 128 + c4];
            __nv_bfloat162 h0 = __floats2bfloat162_rn(x.x, x.y);
            __nv_bfloat162 h1 = __floats2bfloat162_rn(x.z, x.w);
            uint2 pk = make_uint2(*(uint32_t*)&h0, *(uint32_t*)&h1);
            *(uint2*)&Bs[row][c4 * 4] = pk;
        }
    }
    __syncthreads();

    // ================= Mainloop: 32 k-steps, no syncs =========================
    float acc[2][4] = {};
    const int a_row = 16 * wm + (lane & 7) + ((lane >> 3) & 1) * 8;
    const int a_k8  = (lane >> 4) * 8;
    const int b_row = 16 * wn + (lane & 7) + (lane >> 4) * 8;
    const int b_k8  = ((lane >> 3) & 1) * 8;

    const uint32_t abase = (uint32_t)__cvta_generic_to_shared(&As[a_row][a_k8]);
    const uint32_t bbase = (uint32_t)__cvta_generic_to_shared(&Bs[b_row][b_k8]);

    #pragma unroll
    for (int kk = 0; kk < 32; kk++) {
        const uint32_t koff = kk * 16 * 2;   // bytes
        uint32_t a0, a1, a2, a3, b0, b1, b2, b3;
        asm volatile("ldmatrix.sync.aligned.m8n8.x4.shared.b16 {%0,%1,%2,%3}, [%4];\n"
                     : "=r"(a0), "=r"(a1), "=r"(a2), "=r"(a3) : "r"(abase + koff));
        asm volatile("ldmatrix.sync.aligned.m8n8.x4.shared.b16 {%0,%1,%2,%3}, [%4];\n"
                     : "=r"(b0), "=r"(b1), "=r"(b2), "=r"(b3) : "r"(bbase + koff));
        asm volatile("mma.sync.aligned.m16n8k16.row.col.f32.bf16.bf16.f32 "
                     "{%0,%1,%2,%3}, {%4,%5,%6,%7}, {%8,%9}, {%0,%1,%2,%3};\n"
                     : "+f"(acc[0][0]), "+f"(acc[0][1]), "+f"(acc[0][2]), "+f"(acc[0][3])
                     : "r"(a0), "r"(a1), "r"(a2), "r"(a3), "r"(b0), "r"(b1));
        asm volatile("mma.sync.aligned.m16n8k16.row.col.f32.bf16.bf16.f32 "
                     "{%0,%1,%2,%3}, {%4,%5,%6,%7}, {%8,%9}, {%0,%1,%2,%3};\n"
                     : "+f"(acc[1][0]), "+f"(acc[1][1]), "+f"(acc[1][2]), "+f"(acc[1][3])
                     : "r"(a0), "r"(a1), "r"(a2), "r"(a3), "r"(b2), "r"(b3));
    }

    // ================= Epilogue: write S tile =================================
    {
        const int g = lane >> 2, t = lane & 3;
        const int row0 = mTile + 16 * wm + g;
        #pragma unroll
        for (int h = 0; h < 2; h++) {
            const int col = nTile + 16 * wn + 8 * h + t * 2;
            *(float2*)&g_S[row0 * BATCH + col]       = make_float2(acc[h][0], acc[h][1]);
            *(float2*)&g_S[(row0 + 8) * BATCH + col] = make_float2(acc[h][2], acc[h][3]);
        }
    }
    __syncthreads();

    // ================= Grid barrier (epoch-based) =============================
    if (tid == 0) {
        __threadfence();
        const unsigned ep0 = ep0_sm;
        const unsigned prev = atomicAdd(&g_ctr, 1);
        if (prev == NBLK - 1) {
            g_ctr = 0;
            __threadfence();
            g_epoch = ep0 + 1;
        } else {
            while (g_epoch == ep0) {}
        }
        __threadfence();
    }
    __syncthreads();

    // ================= Phase 2: 4 rows per block (validated) ==================
    const int row_l = tid >> 6;
    const int c     = tid & 63;
    const int r     = bid * 4 + row_l;
    const float4* S4 = (const float4*)(g_S + r * BATCH);
    const float4 v1 = S4[c];
    const float4 v2 = S4[c + 64];

    const int b0c = r & ~7;
    const int rc0 = b0c >> 2;
    if (rc0 < 64) {
        if (c == rc0)      *(float4*)&refs[row_l][0] = v1;
        if (c == rc0 + 1)  *(float4*)&refs[row_l][4] = v1;
    } else {
        if (c == rc0 - 64) *(float4*)&refs[row_l][0] = v2;
        if (c == rc0 - 63) *(float4*)&refs[row_l][4] = v2;
    }
    __syncthreads();

    float p[8];
    #pragma unroll
    for (int j = 0; j < 8; j++) p[j] = refs[row_l][j];

    float s8[8];
    #pragma unroll
    for (int j = 0; j < 8; j++) {
        s8[j] = fmaxf(v1.x - p[j], 0.f) + fmaxf(v1.y - p[j], 0.f)
              + fmaxf(v1.z - p[j], 0.f) + fmaxf(v1.w - p[j], 0.f)
              + fmaxf(v2.x - p[j], 0.f) + fmaxf(v2.y - p[j], 0.f)
              + fmaxf(v2.z - p[j], 0.f) + fmaxf(v2.w - p[j], 0.f);
    }
    #pragma unroll
    for (int o = 16; o > 0; o >>= 1)
        #pragma unroll
        for (int j = 0; j < 8; j++)
            s8[j] += __shfl_down_sync(0xffffffffu, s8[j], o);
    if (lane == 0) {
        #pragma unroll
        for (int j = 0; j < 8; j++) wr[warp][j] = s8[j];
    }
    __syncthreads();

    float ratio = 0.f;
    if (tid < 32) {
        const int rl = tid >> 3, j = tid & 7;
        const float rk = 1.f + wr[rl * 2][j] + wr[rl * 2 + 1][j];
        const float pj = refs[rl][j];
        float ps = 0.f;
        #pragma unroll
        for (int k = 0; k < 8; k++) ps += fmaxf(refs[rl][k] - pj, 0.f);
        ratio = (1.f + ps) / rk;
    }
    #pragma unroll
    for (int o = 16; o > 0; o >>= 1)
        ratio += __shfl_down_sync(0xffffffffu, ratio, o);

    if (tid == 0) {
        g_partial[bid] = ratio;
        __threadfence();
        const unsigned prev = atomicAdd(&g_done, 1);
        last_sm = (prev == NBLK - 1) ? 1 : 0;
        if (last_sm) __threadfence();
    }
    __syncthreads();

    if (last_sm) {
        float v = (tid < NBLK) ? g_partial[tid] : 0.f;
        #pragma unroll
        for (int o = 16; o > 0; o >>= 1)
            v += __shfl_down_sync(0xffffffffu, v, o);
        if (lane == 0) warp_sums[warp] = v;
        __syncthreads();
        if (tid == 0) {
            float tot = 0.f;
            #pragma unroll
            for (int w = 0; w < 8; w++) tot += warp_sums[w];
            out[0] = 1.f - tot * (1.f / 4096.f);
            g_done = 0;
        }
    }
}

extern "C" void kernel_launch(void* const* d_in, const int* in_sizes, int n_in,
                              void* d_out, int out_size) {
    const float* fs = (const float*)d_in[0];
    const float* ft = (const float*)d_in[1];
    float* out = (float*)d_out;

    cudaFuncSetAttribute(fused_kernel,
                         cudaFuncAttributeMaxDynamicSharedMemorySize, SMEM_TOTAL);
    fused_kernel<<<dim3(16, 8), 256, SMEM_TOTAL>>>(fs, ft, out);
}